// round 14
// baseline (speedup 1.0000x reference)
#include <cuda_runtime.h>
#include <cuda_fp16.h>
#include <math.h>
#include <stdint.h>

// Problem constants
#define BB 2
#define SS 4096
#define EE 768
#define HH 12
#define DD 64
#define WW 256
#define ROWS (BB*SS)          // 8192
#define C3 (3*EE)             // 2304
#define E4 (4*EE)             // 3072

// ---------------- scratch (static device allocations) ----------------
__device__ __half g_buf_h   [ROWS * EE];   // LN outputs (GEMM A input)
__device__ __half g_buf_qkv [ROWS * C3];
__device__ __half g_buf_attn[ROWS * EE];
__device__ float  g_buf_x1  [ROWS * EE];   // residual stream stays fp32
__device__ __half g_buf_ff  [ROWS * E4];
// transposed fp16 weights [N,K] row-major (K contiguous)
__device__ __half g_wT_attn [C3 * EE];
__device__ __half g_wT_proj [EE * EE];
__device__ __half g_wT_fc   [E4 * EE];
__device__ __half g_wT_proj2[EE * E4];

// ---------------- asm helpers ----------------
__device__ __forceinline__ void mma_f16(float c[4], const uint32_t a[4],
                                        uint32_t b0, uint32_t b1) {
    asm volatile(
        "mma.sync.aligned.m16n8k16.row.col.f32.f16.f16.f32 "
        "{%0,%1,%2,%3}, {%4,%5,%6,%7}, {%8,%9}, {%0,%1,%2,%3};"
        : "+f"(c[0]), "+f"(c[1]), "+f"(c[2]), "+f"(c[3])
        : "r"(a[0]), "r"(a[1]), "r"(a[2]), "r"(a[3]), "r"(b0), "r"(b1));
}

__device__ __forceinline__ void ldsm4(uint32_t r[4], uint32_t addr) {
    asm volatile("ldmatrix.sync.aligned.m8n8.x4.shared.b16 {%0,%1,%2,%3}, [%4];"
                 : "=r"(r[0]), "=r"(r[1]), "=r"(r[2]), "=r"(r[3]) : "r"(addr));
}

__device__ __forceinline__ void ldsm4t(uint32_t r[4], uint32_t addr) {
    asm volatile("ldmatrix.sync.aligned.m8n8.x4.trans.shared.b16 {%0,%1,%2,%3}, [%4];"
                 : "=r"(r[0]), "=r"(r[1]), "=r"(r[2]), "=r"(r[3]) : "r"(addr));
}

__device__ __forceinline__ void cp16(uint32_t saddr, const void* gptr) {
    asm volatile("cp.async.cg.shared.global [%0], [%1], 16;\n"
                 :: "r"(saddr), "l"(gptr));
}
__device__ __forceinline__ void cp_commit() {
    asm volatile("cp.async.commit_group;\n" ::: "memory");
}

__device__ __forceinline__ float ex2(float x) {
    float y;
    asm("ex2.approx.ftz.f32 %0, %1;" : "=f"(y) : "f"(x));
    return y;
}

// pack two floats to one fp16x2 register (full 32 bits)
__device__ __forceinline__ uint32_t pack_h2(float a, float b) {
    __half2 t = __floats2half2_rn(a, b);
    return *reinterpret_cast<uint32_t*>(&t);
}

// shared 128B-row swizzle: row r (128 B), 16B chunk c: conflict-free ldmatrix
__device__ __forceinline__ uint32_t arow_off(int r, int c) {
    return (uint32_t)(r * 128 + ((c ^ (r & 7)) << 4));
}

// ---------------- LayerNorm (fp32 in, fp16 out) ----------------
__global__ __launch_bounds__(256)
void ln_kernel(const float* __restrict__ x, const float* __restrict__ g,
               const float* __restrict__ b, __half* __restrict__ out)
{
    const int row = blockIdx.x;
    const int tid = threadIdx.x;
    const float* xr = x + (long)row * EE;
    float v0 = xr[tid], v1 = xr[tid + 256], v2 = xr[tid + 512];
    float s  = v0 + v1 + v2;
    float sq = v0*v0 + v1*v1 + v2*v2;

    __shared__ float sh_s[8], sh_q[8];
    #pragma unroll
    for (int o = 16; o > 0; o >>= 1) {
        s  += __shfl_xor_sync(0xffffffffu, s,  o);
        sq += __shfl_xor_sync(0xffffffffu, sq, o);
    }
    const int wid = tid >> 5, lane = tid & 31;
    if (lane == 0) { sh_s[wid] = s; sh_q[wid] = sq; }
    __syncthreads();
    if (wid == 0) {
        s  = (lane < 8) ? sh_s[lane] : 0.f;
        sq = (lane < 8) ? sh_q[lane] : 0.f;
        #pragma unroll
        for (int o = 4; o > 0; o >>= 1) {
            s  += __shfl_xor_sync(0xffffffffu, s,  o);
            sq += __shfl_xor_sync(0xffffffffu, sq, o);
        }
        if (lane == 0) { sh_s[0] = s; sh_q[0] = sq; }
    }
    __syncthreads();
    const float mean = sh_s[0] * (1.f / EE);
    const float var  = sh_q[0] * (1.f / EE) - mean * mean;
    const float inv  = rsqrtf(var + 1e-5f);

    __half* orow = out + (long)row * EE;
    orow[tid      ] = __float2half_rn((v0 - mean) * inv * g[tid      ] + b[tid      ]);
    orow[tid + 256] = __float2half_rn((v1 - mean) * inv * g[tid + 256] + b[tid + 256]);
    orow[tid + 512] = __float2half_rn((v2 - mean) * inv * g[tid + 512] + b[tid + 512]);
}

// ---------------- merged weight transpose+convert (all 4 weights) ---------
// segment s: in fp32 [K,N] -> out fp16 [N,K]
#define NT0 ((C3/32)*(EE/32))   // 1728
#define NT1 ((EE/32)*(EE/32))   // 576
#define NT2 ((E4/32)*(EE/32))   // 2304
#define NT3 ((EE/32)*(E4/32))   // 2304
__global__ __launch_bounds__(256)
void transpose_all(const float* __restrict__ w0, __half* __restrict__ o0,
                   const float* __restrict__ w1, __half* __restrict__ o1,
                   const float* __restrict__ w2, __half* __restrict__ o2,
                   const float* __restrict__ w3, __half* __restrict__ o3)
{
    __shared__ float tile[32][33];
    int id = blockIdx.x;
    const float* in; __half* out; int K, N;
    if (id < NT0)                     { in = w0; out = o0; K = EE; N = C3; }
    else if ((id -= NT0) < NT1)       { in = w1; out = o1; K = EE; N = EE; }
    else if ((id -= NT1) < NT2)       { in = w2; out = o2; K = EE; N = E4; }
    else { id -= NT2;                   in = w3; out = o3; K = E4; N = EE; }
    const int nx = N / 32;
    const int bx = (id % nx) * 32;    // N
    const int by = (id / nx) * 32;    // K
    const int tx = threadIdx.x & 31, ty = threadIdx.x >> 5;
    #pragma unroll
    for (int i = ty; i < 32; i += 8)
        tile[i][tx] = in[(long)(by + i) * N + bx + tx];
    __syncthreads();
    #pragma unroll
    for (int i = ty; i < 32; i += 8)
        out[(long)(bx + i) * K + by + tx] = __float2half_rn(tile[tx][i]);
}

// ---------------- fp16 HMMA GEMM -----------------------------------------
// 128x128 tile, BK=64, 256 threads = 8 warps (4x2), warp tile 32x64.
// 3-stage cp.async, 128B-row swizzle, 2 CTAs/SM.
// EPI: 0 = +bias -> half   1 = +bias+res(fp32) -> float   2 = gelu -> half
#define GBK 64
#define GASTG (128 * 128)
#define GBSTG (128 * 128)
#define GSTG  (GASTG + GBSTG)
#define GNST  3
#define HG_SMEM (GNST * GSTG)      // 98304 B

template<int EPI>
__global__ __launch_bounds__(256, 2)
void hgemm(const __half* __restrict__ A, const __half* __restrict__ Bt,
           const float* __restrict__ bias, const float* __restrict__ R,
           void* __restrict__ Cout, int M, int N, int K)
{
    extern __shared__ char smem[];
    const uint32_t sb = (uint32_t)__cvta_generic_to_shared(smem);

    const int tid  = threadIdx.x;
    const int warp = tid >> 5;
    const int lane = tid & 31;
    const int g    = lane >> 2;
    const int tg   = lane & 3;
    const int wm   = warp >> 1;   // 0..3 (M)
    const int wn   = warp & 1;    // 0..1 (N)

    const int bm = blockIdx.y * 128;
    const int bn = blockIdx.x * 128;

    const int T = K / GBK;

    auto issue = [&](int s) {
        const uint32_t dst = sb + (s % GNST) * GSTG;
        #pragma unroll
        for (int i = 0; i < 4; i++) {
            const int id = tid + i * 256;
            const int r = id >> 3, c = id & 7;
            cp16(dst + arow_off(r, c),
                 (const char*)A + (((long)(bm + r) * K + s * GBK + c * 8) << 1));
        }
        #pragma unroll
        for (int i = 0; i < 4; i++) {
            const int id = tid + i * 256;
            const int r = id >> 3, c = id & 7;
            cp16(dst + GASTG + arow_off(r, c),
                 (const char*)Bt + (((long)(bn + r) * K + s * GBK + c * 8) << 1));
        }
    };

    issue(0); cp_commit();
    issue(1); cp_commit();

    float acc[2][8][4] = {};

    for (int t = 0; t < T; t++) {
        asm volatile("cp.async.wait_group 1;" ::: "memory");
        __syncthreads();
        if (t + 2 < T) issue(t + 2);
        cp_commit();

        const uint32_t sA = sb + (t % GNST) * GSTG;
        const uint32_t sB = sA + GASTG;

        #pragma unroll
        for (int ks = 0; ks < 4; ks++) {
            uint32_t af[2][4];
            #pragma unroll
            for (int mi = 0; mi < 2; mi++) {
                const int row = wm * 32 + mi * 16 + (lane & 7) + ((lane >> 3) & 1) * 8;
                const int ch  = 2 * ks + (lane >> 4);
                ldsm4(af[mi], sA + arow_off(row, ch));
            }
            uint32_t bf[4][4];
            #pragma unroll
            for (int n2 = 0; n2 < 4; n2++) {
                const int row = wn * 64 + n2 * 16 + (lane & 7) + ((lane >> 3) & 1) * 8;
                const int ch  = 2 * ks + (lane >> 4);
                ldsm4(bf[n2], sB + arow_off(row, ch));
            }
            #pragma unroll
            for (int ni = 0; ni < 8; ni++) {
                const uint32_t b0 = bf[ni >> 1][ni & 1];
                const uint32_t b1 = bf[ni >> 1][2 + (ni & 1)];
                #pragma unroll
                for (int mi = 0; mi < 2; mi++)
                    mma_f16(acc[mi][ni], af[mi], b0, b1);
            }
        }
    }

    #pragma unroll
    for (int mi = 0; mi < 2; mi++) {
        const int r0 = bm + wm * 32 + mi * 16 + g;
        #pragma unroll
        for (int ni = 0; ni < 8; ni++) {
            const int cn = bn + wn * 64 + ni * 8 + 2 * tg;
            const float bz0 = bias[cn], bz1 = bias[cn + 1];
            float v00 = acc[mi][ni][0] + bz0;
            float v01 = acc[mi][ni][1] + bz1;
            float v10 = acc[mi][ni][2] + bz0;
            float v11 = acc[mi][ni][3] + bz1;
            const long o0 = (long)r0 * N + cn;
            const long o1 = (long)(r0 + 8) * N + cn;
            if (EPI == 1) {
                v00 += R[o0]; v01 += R[o0 + 1];
                v10 += R[o1]; v11 += R[o1 + 1];
                float* C = (float*)Cout;
                *(float2*)&C[o0] = make_float2(v00, v01);
                *(float2*)&C[o1] = make_float2(v10, v11);
            } else {
                if (EPI == 2) {
                    v00 = 0.5f * v00 * (1.f + erff(v00 * 0.70710678118654752f));
                    v01 = 0.5f * v01 * (1.f + erff(v01 * 0.70710678118654752f));
                    v10 = 0.5f * v10 * (1.f + erff(v10 * 0.70710678118654752f));
                    v11 = 0.5f * v11 * (1.f + erff(v11 * 0.70710678118654752f));
                }
                __half* C = (__half*)Cout;
                *(__half2*)&C[o0] = __floats2half2_rn(v00, v01);
                *(__half2*)&C[o1] = __floats2half2_rn(v10, v11);
            }
        }
    }
}

// ---------------- Flash attention with fp16 HMMA ---------------------------
// 128 query rows / CTA, 256 threads = 8 warps (16 q-rows each).
// K-tiles of 64; 10-tile window; tiles 2..7 unmasked.
#define ASC 0.18033688011112042f   // 0.125 * log2(e)
// dynamic smem: Q 16KB | K0 8KB | V0 8KB | K1 8KB | V1 8KB = 48KB
#define AT_Q  0
#define AT_K0 16384
#define AT_V0 24576
#define AT_K1 32768
#define AT_V1 40960
#define AT_SMEM 49152

__global__ __launch_bounds__(256)
void attn_kernel(const __half* __restrict__ qkv, __half* __restrict__ out)
{
    extern __shared__ char asmem[];
    const uint32_t sbase = (uint32_t)__cvta_generic_to_shared(asmem);
    const uint32_t sQb = sbase + AT_Q;
    const uint32_t sKb[2] = { sbase + AT_K0, sbase + AT_K1 };
    const uint32_t sVb[2] = { sbase + AT_V0, sbase + AT_V1 };

    const int qt = blockIdx.x, h = blockIdx.y, b = blockIdx.z;
    const int qb = qt * 128;
    const int tid = threadIdx.x;
    const int w = tid >> 5, lane = tid & 31;
    const int g = lane >> 2, tg = lane & 3;

    const long rowbase = (long)(b * SS);
    const __half* Qg = qkv + h * DD;
    const __half* Kg = qkv + EE + h * DD;
    const __half* Vg = qkv + 2 * EE + h * DD;

    // tiles t: kbase = qb - 256 + 64t, t in [tstart, tend] (of 0..9)
    const int tstart = (qb >= 193) ? 0 : (193 - qb + 63) / 64;
    const int tend   = min(9, (4351 - qb) / 64);

    // load Q tile (128 rows x 128B): 4 chunks/thread
    #pragma unroll
    for (int i = 0; i < 4; i++) {
        const int id = tid + i * 256, r = id >> 3, c = id & 7;
        cp16(sQb + arow_off(r, c), (const char*)(Qg + (rowbase + qb + r) * C3) + c * 16);
    }
    // K/V loader: 64 rows each, 2 chunks K + 2 chunks V per thread
    auto issue = [&](int t, int buf) {
        const int kbase = qb - 256 + 64 * t;
        #pragma unroll
        for (int i = 0; i < 2; i++) {
            const int id = tid + i * 256, r = id >> 3, c = id & 7;
            int j = kbase + r; j = j < 0 ? 0 : (j >= SS ? SS - 1 : j);
            cp16(sKb[buf] + arow_off(r, c), (const char*)(Kg + (rowbase + j) * C3) + c * 16);
            cp16(sVb[buf] + arow_off(r, c), (const char*)(Vg + (rowbase + j) * C3) + c * 16);
        }
    };

    issue(tstart, 0);
    cp_commit();

    uint32_t aq[4][4];
    float acc_o[8][4] = {};
    float m0 = -1e30f, m1 = -1e30f, l0 = 0.f, l1 = 0.f;
    const int i0 = qb + w * 16 + g;
    const int i1 = i0 + 8;

    for (int t = tstart; t <= tend; t++) {
        const int buf = (t - tstart) & 1;
        if (t < tend) { issue(t + 1, buf ^ 1); cp_commit(); }
        if (t < tend) asm volatile("cp.async.wait_group 1;" ::: "memory");
        else          asm volatile("cp.async.wait_group 0;" ::: "memory");
        __syncthreads();

        if (t == tstart) {
            #pragma unroll
            for (int ks = 0; ks < 4; ks++) {
                const int row = w * 16 + (lane & 7) + ((lane >> 3) & 1) * 8;
                const int ch  = 2 * ks + (lane >> 4);
                ldsm4(aq[ks], sQb + arow_off(row, ch));
            }
        }

        const int kbase = qb - 256 + 64 * t;

        // ---- scores S = Q K^T ----
        float s[8][4] = {};
        #pragma unroll
        for (int ks = 0; ks < 4; ks++) {
            uint32_t bk[4][4];
            #pragma unroll
            for (int n2 = 0; n2 < 4; n2++) {
                const int row = n2 * 16 + (lane & 7) + ((lane >> 3) & 1) * 8;
                const int ch  = 2 * ks + (lane >> 4);
                ldsm4(bk[n2], sKb[buf] + arow_off(row, ch));
            }
            #pragma unroll
            for (int ni = 0; ni < 8; ni++)
                mma_f16(s[ni], aq[ks], bk[ni >> 1][ni & 1], bk[ni >> 1][2 + (ni & 1)]);
        }

        // ---- mask (tiles fully inside window & seq: 2..7 interior) ----
        const bool masked = (t <= 1) | (t >= 8) | (kbase < 0) | (kbase + 63 >= SS);
        if (masked) {
            #pragma unroll
            for (int ni = 0; ni < 8; ni++) {
                #pragma unroll
                for (int c = 0; c < 2; c++) {
                    const int j = kbase + ni * 8 + 2 * tg + c;
                    const bool inseq = (j >= 0) & (j < SS);
                    if (!(inseq & (j >= i0 - WW) & (j <= i0 + WW))) s[ni][c]     = -1e30f;
                    if (!(inseq & (j >= i1 - WW) & (j <= i1 + WW))) s[ni][c + 2] = -1e30f;
                }
            }
        }

        // ---- online softmax ----
        float mx0 = s[0][0], mx1 = s[0][2];
        #pragma unroll
        for (int ni = 0; ni < 8; ni++) {
            mx0 = fmaxf(mx0, fmaxf(s[ni][0], s[ni][1]));
            mx1 = fmaxf(mx1, fmaxf(s[ni][2], s[ni][3]));
        }
        mx0 = fmaxf(mx0, __shfl_xor_sync(0xffffffffu, mx0, 1));
        mx0 = fmaxf(mx0, __shfl_xor_sync(0xffffffffu, mx0, 2));
        mx1 = fmaxf(mx1, __shfl_xor_sync(0xffffffffu, mx1, 1));
        mx1 = fmaxf(mx1, __shfl_xor_sync(0xffffffffu, mx1, 2));
        const float mn0 = fmaxf(m0, mx0), mn1 = fmaxf(m1, mx1);
        const float f0 = ex2((m0 - mn0) * ASC), f1 = ex2((m1 - mn1) * ASC);
        m0 = mn0; m1 = mn1;

        float ps0 = 0.f, ps1 = 0.f;
        #pragma unroll
        for (int ni = 0; ni < 8; ni++) {
            s[ni][0] = ex2((s[ni][0] - mn0) * ASC);
            s[ni][1] = ex2((s[ni][1] - mn0) * ASC);
            s[ni][2] = ex2((s[ni][2] - mn1) * ASC);
            s[ni][3] = ex2((s[ni][3] - mn1) * ASC);
            ps0 += s[ni][0] + s[ni][1];
            ps1 += s[ni][2] + s[ni][3];
        }
        // per-thread partials; quad-reduced once after the loop
        l0 = l0 * f0 + ps0;
        l1 = l1 * f1 + ps1;
        #pragma unroll
        for (int nd = 0; nd < 8; nd++) {
            acc_o[nd][0] *= f0; acc_o[nd][1] *= f0;
            acc_o[nd][2] *= f1; acc_o[nd][3] *= f1;
        }

        // ---- PV: O += P V ----
        #pragma unroll
        for (int kk = 0; kk < 4; kk++) {
            uint32_t pa[4];
            pa[0] = pack_h2(s[2*kk][0],   s[2*kk][1]);
            pa[1] = pack_h2(s[2*kk][2],   s[2*kk][3]);
            pa[2] = pack_h2(s[2*kk+1][0], s[2*kk+1][1]);
            pa[3] = pack_h2(s[2*kk+1][2], s[2*kk+1][3]);
            #pragma unroll
            for (int d2 = 0; d2 < 4; d2++) {
                uint32_t bv[4];
                const int row = kk * 16 + (lane & 7) + ((lane >> 3) & 1) * 8;
                const int ch  = 2 * d2 + (lane >> 4);
                ldsm4t(bv, sVb[buf] + arow_off(row, ch));
                mma_f16(acc_o[2 * d2],     pa, bv[0], bv[1]);
                mma_f16(acc_o[2 * d2 + 1], pa, bv[2], bv[3]);
            }
        }
        __syncthreads();
    }

    // reduce softmax denominator across the quad
    l0 += __shfl_xor_sync(0xffffffffu, l0, 1);
    l0 += __shfl_xor_sync(0xffffffffu, l0, 2);
    l1 += __shfl_xor_sync(0xffffffffu, l1, 1);
    l1 += __shfl_xor_sync(0xffffffffu, l1, 2);

    // ---- write out ----
    const float r0 = 1.f / l0, r1 = 1.f / l1;
    __half* o0 = out + (rowbase + i0) * EE + h * DD + 2 * tg;
    __half* o1 = out + (rowbase + i1) * EE + h * DD + 2 * tg;
    #pragma unroll
    for (int nd = 0; nd < 8; nd++) {
        *(__half2*)(o0 + nd * 8) = __floats2half2_rn(acc_o[nd][0] * r0, acc_o[nd][1] * r0);
        *(__half2*)(o1 + nd * 8) = __floats2half2_rn(acc_o[nd][2] * r1, acc_o[nd][3] * r1);
    }
}

// ---------------- launch ----------------
extern "C" void kernel_launch(void* const* d_in, const int* in_sizes, int n_in,
                              void* d_out, int out_size)
{
    const float* x        = (const float*)d_in[0];
    const float* ln1_g    = (const float*)d_in[1];
    const float* ln1_b    = (const float*)d_in[2];
    const float* c_attn_w = (const float*)d_in[3];
    const float* c_attn_b = (const float*)d_in[4];
    const float* c_proj_w = (const float*)d_in[5];
    const float* c_proj_b = (const float*)d_in[6];
    const float* ln2_g    = (const float*)d_in[7];
    const float* ln2_b    = (const float*)d_in[8];
    const float* fc_w     = (const float*)d_in[9];
    const float* fc_b     = (const float*)d_in[10];
    const float* proj2_w  = (const float*)d_in[11];
    const float* proj2_b  = (const float*)d_in[12];
    float* out = (float*)d_out;

    __half *h, *qkv, *attn, *ff;
    float *x1;
    __half *wT_attn, *wT_proj, *wT_fc, *wT_proj2;
    cudaGetSymbolAddress((void**)&h,    g_buf_h);
    cudaGetSymbolAddress((void**)&qkv,  g_buf_qkv);
    cudaGetSymbolAddress((void**)&attn, g_buf_attn);
    cudaGetSymbolAddress((void**)&x1,   g_buf_x1);
    cudaGetSymbolAddress((void**)&ff,   g_buf_ff);
    cudaGetSymbolAddress((void**)&wT_attn,  g_wT_attn);
    cudaGetSymbolAddress((void**)&wT_proj,  g_wT_proj);
    cudaGetSymbolAddress((void**)&wT_fc,    g_wT_fc);
    cudaGetSymbolAddress((void**)&wT_proj2, g_wT_proj2);

    cudaFuncSetAttribute(hgemm<0>, cudaFuncAttributeMaxDynamicSharedMemorySize, HG_SMEM);
    cudaFuncSetAttribute(hgemm<1>, cudaFuncAttributeMaxDynamicSharedMemorySize, HG_SMEM);
    cudaFuncSetAttribute(hgemm<2>, cudaFuncAttributeMaxDynamicSharedMemorySize, HG_SMEM);
    cudaFuncSetAttribute(attn_kernel, cudaFuncAttributeMaxDynamicSharedMemorySize, AT_SMEM);

    transpose_all<<<NT0 + NT1 + NT2 + NT3, 256>>>(
        c_attn_w, wT_attn, c_proj_w, wT_proj, fc_w, wT_fc, proj2_w, wT_proj2);

    ln_kernel<<<ROWS, 256>>>(x, ln1_g, ln1_b, h);
    hgemm<0><<<dim3(C3 / 128, ROWS / 128), 256, HG_SMEM>>>(
        h, wT_attn, c_attn_b, nullptr, qkv, ROWS, C3, EE);
    attn_kernel<<<dim3(SS / 128, HH, BB), 256, AT_SMEM>>>(qkv, attn);
    hgemm<1><<<dim3(EE / 128, ROWS / 128), 256, HG_SMEM>>>(
        attn, wT_proj, c_proj_b, x, x1, ROWS, EE, EE);
    ln_kernel<<<ROWS, 256>>>(x1, ln2_g, ln2_b, h);
    hgemm<2><<<dim3(E4 / 128, ROWS / 128), 256, HG_SMEM>>>(
        h, wT_fc, fc_b, nullptr, ff, ROWS, E4, EE);
    hgemm<1><<<dim3(EE / 128, ROWS / 128), 256, HG_SMEM>>>(
        ff, wT_proj2, proj2_b, x1, out, ROWS, EE, E4);
}

// round 15
// speedup vs baseline: 1.0239x; 1.0239x over previous
#include <cuda_runtime.h>
#include <cuda_fp16.h>
#include <math.h>
#include <stdint.h>

// Problem constants
#define BB 2
#define SS 4096
#define EE 768
#define HH 12
#define DD 64
#define WW 256
#define ROWS (BB*SS)          // 8192
#define C3 (3*EE)             // 2304
#define E4 (4*EE)             // 3072

// ---------------- scratch (static device allocations) ----------------
__device__ __half g_buf_h   [ROWS * EE];   // LN outputs (GEMM A input)
__device__ __half g_buf_qkv [ROWS * C3];
__device__ __half g_buf_attn[ROWS * EE];
__device__ float  g_buf_x1  [ROWS * EE];   // residual stream stays fp32
__device__ __half g_buf_ff  [ROWS * E4];
// transposed fp16 weights [N,K] row-major (K contiguous)
__device__ __half g_wT_attn [C3 * EE];
__device__ __half g_wT_proj [EE * EE];
__device__ __half g_wT_fc   [E4 * EE];
__device__ __half g_wT_proj2[EE * E4];

// ---------------- asm helpers ----------------
__device__ __forceinline__ void mma_f16(float c[4], const uint32_t a[4],
                                        uint32_t b0, uint32_t b1) {
    asm volatile(
        "mma.sync.aligned.m16n8k16.row.col.f32.f16.f16.f32 "
        "{%0,%1,%2,%3}, {%4,%5,%6,%7}, {%8,%9}, {%0,%1,%2,%3};"
        : "+f"(c[0]), "+f"(c[1]), "+f"(c[2]), "+f"(c[3])
        : "r"(a[0]), "r"(a[1]), "r"(a[2]), "r"(a[3]), "r"(b0), "r"(b1));
}

__device__ __forceinline__ void ldsm4(uint32_t r[4], uint32_t addr) {
    asm volatile("ldmatrix.sync.aligned.m8n8.x4.shared.b16 {%0,%1,%2,%3}, [%4];"
                 : "=r"(r[0]), "=r"(r[1]), "=r"(r[2]), "=r"(r[3]) : "r"(addr));
}

__device__ __forceinline__ void ldsm4t(uint32_t r[4], uint32_t addr) {
    asm volatile("ldmatrix.sync.aligned.m8n8.x4.trans.shared.b16 {%0,%1,%2,%3}, [%4];"
                 : "=r"(r[0]), "=r"(r[1]), "=r"(r[2]), "=r"(r[3]) : "r"(addr));
}

__device__ __forceinline__ void cp16(uint32_t saddr, const void* gptr) {
    asm volatile("cp.async.cg.shared.global [%0], [%1], 16;\n"
                 :: "r"(saddr), "l"(gptr));
}
__device__ __forceinline__ void cp_commit() {
    asm volatile("cp.async.commit_group;\n" ::: "memory");
}

__device__ __forceinline__ float ex2(float x) {
    float y;
    asm("ex2.approx.ftz.f32 %0, %1;" : "=f"(y) : "f"(x));
    return y;
}

// pack two floats to one fp16x2 register (full 32 bits)
__device__ __forceinline__ uint32_t pack_h2(float a, float b) {
    __half2 t = __floats2half2_rn(a, b);
    return *reinterpret_cast<uint32_t*>(&t);
}

// shared 128B-row swizzle: row r (128 B), 16B chunk c: conflict-free ldmatrix
__device__ __forceinline__ uint32_t arow_off(int r, int c) {
    return (uint32_t)(r * 128 + ((c ^ (r & 7)) << 4));
}

// ---------------- LayerNorm (fp32 in, fp16 out) ----------------
__global__ __launch_bounds__(256)
void ln_kernel(const float* __restrict__ x, const float* __restrict__ g,
               const float* __restrict__ b, __half* __restrict__ out)
{
    const int row = blockIdx.x;
    const int tid = threadIdx.x;
    const float* xr = x + (long)row * EE;
    float v0 = xr[tid], v1 = xr[tid + 256], v2 = xr[tid + 512];
    float s  = v0 + v1 + v2;
    float sq = v0*v0 + v1*v1 + v2*v2;

    __shared__ float sh_s[8], sh_q[8];
    #pragma unroll
    for (int o = 16; o > 0; o >>= 1) {
        s  += __shfl_xor_sync(0xffffffffu, s,  o);
        sq += __shfl_xor_sync(0xffffffffu, sq, o);
    }
    const int wid = tid >> 5, lane = tid & 31;
    if (lane == 0) { sh_s[wid] = s; sh_q[wid] = sq; }
    __syncthreads();
    if (wid == 0) {
        s  = (lane < 8) ? sh_s[lane] : 0.f;
        sq = (lane < 8) ? sh_q[lane] : 0.f;
        #pragma unroll
        for (int o = 4; o > 0; o >>= 1) {
            s  += __shfl_xor_sync(0xffffffffu, s,  o);
            sq += __shfl_xor_sync(0xffffffffu, sq, o);
        }
        if (lane == 0) { sh_s[0] = s; sh_q[0] = sq; }
    }
    __syncthreads();
    const float mean = sh_s[0] * (1.f / EE);
    const float var  = sh_q[0] * (1.f / EE) - mean * mean;
    const float inv  = rsqrtf(var + 1e-5f);

    __half* orow = out + (long)row * EE;
    orow[tid      ] = __float2half_rn((v0 - mean) * inv * g[tid      ] + b[tid      ]);
    orow[tid + 256] = __float2half_rn((v1 - mean) * inv * g[tid + 256] + b[tid + 256]);
    orow[tid + 512] = __float2half_rn((v2 - mean) * inv * g[tid + 512] + b[tid + 512]);
}

// ---------------- merged weight transpose+convert (all 4 weights) ---------
#define NT0 ((C3/32)*(EE/32))   // 1728
#define NT1 ((EE/32)*(EE/32))   // 576
#define NT2 ((E4/32)*(EE/32))   // 2304
#define NT3 ((EE/32)*(E4/32))   // 2304
__global__ __launch_bounds__(256)
void transpose_all(const float* __restrict__ w0, __half* __restrict__ o0,
                   const float* __restrict__ w1, __half* __restrict__ o1,
                   const float* __restrict__ w2, __half* __restrict__ o2,
                   const float* __restrict__ w3, __half* __restrict__ o3)
{
    __shared__ float tile[32][33];
    int id = blockIdx.x;
    const float* in; __half* out; int K, N;
    if (id < NT0)                     { in = w0; out = o0; K = EE; N = C3; }
    else if ((id -= NT0) < NT1)       { in = w1; out = o1; K = EE; N = EE; }
    else if ((id -= NT1) < NT2)       { in = w2; out = o2; K = EE; N = E4; }
    else { id -= NT2;                   in = w3; out = o3; K = E4; N = EE; }
    const int nx = N / 32;
    const int bx = (id % nx) * 32;    // N
    const int by = (id / nx) * 32;    // K
    const int tx = threadIdx.x & 31, ty = threadIdx.x >> 5;
    #pragma unroll
    for (int i = ty; i < 32; i += 8)
        tile[i][tx] = in[(long)(by + i) * N + bx + tx];
    __syncthreads();
    #pragma unroll
    for (int i = ty; i < 32; i += 8)
        out[(long)(bx + i) * K + by + tx] = __float2half_rn(tile[tx][i]);
}

// ---------------- fp16 HMMA GEMM -----------------------------------------
// 128x128 tile, BK=64, 256 threads = 8 warps (4x2), warp tile 32x64.
// 3-stage cp.async, 128B-row swizzle, 2 CTAs/SM.
// EPI: 0 = +bias -> half   1 = +bias+res(fp32) -> float   2 = gelu -> half
#define GBK 64
#define GASTG (128 * 128)
#define GBSTG (128 * 128)
#define GSTG  (GASTG + GBSTG)
#define GNST  3
#define HG_SMEM (GNST * GSTG)      // 98304 B

template<int EPI>
__global__ __launch_bounds__(256, 2)
void hgemm(const __half* __restrict__ A, const __half* __restrict__ Bt,
           const float* __restrict__ bias, const float* __restrict__ R,
           void* __restrict__ Cout, int M, int N, int K)
{
    extern __shared__ char smem[];
    const uint32_t sb = (uint32_t)__cvta_generic_to_shared(smem);

    const int tid  = threadIdx.x;
    const int warp = tid >> 5;
    const int lane = tid & 31;
    const int g    = lane >> 2;
    const int tg   = lane & 3;
    const int wm   = warp >> 1;   // 0..3 (M)
    const int wn   = warp & 1;    // 0..1 (N)

    const int bm = blockIdx.y * 128;
    const int bn = blockIdx.x * 128;

    const int T = K / GBK;

    auto issue = [&](int s) {
        const uint32_t dst = sb + (s % GNST) * GSTG;
        #pragma unroll
        for (int i = 0; i < 4; i++) {
            const int id = tid + i * 256;
            const int r = id >> 3, c = id & 7;
            cp16(dst + arow_off(r, c),
                 (const char*)A + (((long)(bm + r) * K + s * GBK + c * 8) << 1));
        }
        #pragma unroll
        for (int i = 0; i < 4; i++) {
            const int id = tid + i * 256;
            const int r = id >> 3, c = id & 7;
            cp16(dst + GASTG + arow_off(r, c),
                 (const char*)Bt + (((long)(bn + r) * K + s * GBK + c * 8) << 1));
        }
    };

    issue(0); cp_commit();
    issue(1); cp_commit();

    float acc[2][8][4] = {};

    for (int t = 0; t < T; t++) {
        asm volatile("cp.async.wait_group 1;" ::: "memory");
        __syncthreads();
        if (t + 2 < T) issue(t + 2);
        cp_commit();

        const uint32_t sA = sb + (t % GNST) * GSTG;
        const uint32_t sB = sA + GASTG;

        #pragma unroll
        for (int ks = 0; ks < 4; ks++) {
            uint32_t af[2][4];
            #pragma unroll
            for (int mi = 0; mi < 2; mi++) {
                const int row = wm * 32 + mi * 16 + (lane & 7) + ((lane >> 3) & 1) * 8;
                const int ch  = 2 * ks + (lane >> 4);
                ldsm4(af[mi], sA + arow_off(row, ch));
            }
            uint32_t bf[4][4];
            #pragma unroll
            for (int n2 = 0; n2 < 4; n2++) {
                const int row = wn * 64 + n2 * 16 + (lane & 7) + ((lane >> 3) & 1) * 8;
                const int ch  = 2 * ks + (lane >> 4);
                ldsm4(bf[n2], sB + arow_off(row, ch));
            }
            #pragma unroll
            for (int ni = 0; ni < 8; ni++) {
                const uint32_t b0 = bf[ni >> 1][ni & 1];
                const uint32_t b1 = bf[ni >> 1][2 + (ni & 1)];
                #pragma unroll
                for (int mi = 0; mi < 2; mi++)
                    mma_f16(acc[mi][ni], af[mi], b0, b1);
            }
        }
    }

    #pragma unroll
    for (int mi = 0; mi < 2; mi++) {
        const int r0 = bm + wm * 32 + mi * 16 + g;
        #pragma unroll
        for (int ni = 0; ni < 8; ni++) {
            const int cn = bn + wn * 64 + ni * 8 + 2 * tg;
            const float bz0 = bias[cn], bz1 = bias[cn + 1];
            float v00 = acc[mi][ni][0] + bz0;
            float v01 = acc[mi][ni][1] + bz1;
            float v10 = acc[mi][ni][2] + bz0;
            float v11 = acc[mi][ni][3] + bz1;
            const long o0 = (long)r0 * N + cn;
            const long o1 = (long)(r0 + 8) * N + cn;
            if (EPI == 1) {
                v00 += R[o0]; v01 += R[o0 + 1];
                v10 += R[o1]; v11 += R[o1 + 1];
                float* C = (float*)Cout;
                *(float2*)&C[o0] = make_float2(v00, v01);
                *(float2*)&C[o1] = make_float2(v10, v11);
            } else {
                if (EPI == 2) {
                    v00 = 0.5f * v00 * (1.f + erff(v00 * 0.70710678118654752f));
                    v01 = 0.5f * v01 * (1.f + erff(v01 * 0.70710678118654752f));
                    v10 = 0.5f * v10 * (1.f + erff(v10 * 0.70710678118654752f));
                    v11 = 0.5f * v11 * (1.f + erff(v11 * 0.70710678118654752f));
                }
                __half* C = (__half*)Cout;
                *(__half2*)&C[o0] = __floats2half2_rn(v00, v01);
                *(__half2*)&C[o1] = __floats2half2_rn(v10, v11);
            }
        }
    }
}

// ---------------- Flash attention with fp16 HMMA ---------------------------
// 128 query rows / CTA, 256 threads = 8 warps (16 q-rows each), 2 CTAs/SM.
// K-tiles of 64; 10-tile window; tiles 2..7 unmasked.
#define ASC 0.18033688011112042f   // 0.125 * log2(e)
// dynamic smem: Q 16KB | K0 8KB | V0 8KB | K1 8KB | V1 8KB = 48KB
#define AT_Q  0
#define AT_K0 16384
#define AT_V0 24576
#define AT_K1 32768
#define AT_V1 40960
#define AT_SMEM 49152

__global__ __launch_bounds__(256, 2)
void attn_kernel(const __half* __restrict__ qkv, __half* __restrict__ out)
{
    extern __shared__ char asmem[];
    const uint32_t sbase = (uint32_t)__cvta_generic_to_shared(asmem);
    const uint32_t sQb = sbase + AT_Q;
    const uint32_t sKb[2] = { sbase + AT_K0, sbase + AT_K1 };
    const uint32_t sVb[2] = { sbase + AT_V0, sbase + AT_V1 };

    const int qt = blockIdx.x, h = blockIdx.y, b = blockIdx.z;
    const int qb = qt * 128;
    const int tid = threadIdx.x;
    const int w = tid >> 5, lane = tid & 31;
    const int g = lane >> 2, tg = lane & 3;

    const long rowbase = (long)(b * SS);
    const __half* Qg = qkv + h * DD;
    const __half* Kg = qkv + EE + h * DD;
    const __half* Vg = qkv + 2 * EE + h * DD;

    // tiles t: kbase = qb - 256 + 64t, t in [tstart, tend] (of 0..9)
    const int tstart = (qb >= 193) ? 0 : (193 - qb + 63) / 64;
    const int tend   = min(9, (4351 - qb) / 64);

    // load Q tile (128 rows x 128B): 4 chunks/thread
    #pragma unroll
    for (int i = 0; i < 4; i++) {
        const int id = tid + i * 256, r = id >> 3, c = id & 7;
        cp16(sQb + arow_off(r, c), (const char*)(Qg + (rowbase + qb + r) * C3) + c * 16);
    }
    // K/V loader: 64 rows each, 2 chunks K + 2 chunks V per thread
    auto issue = [&](int t, int buf) {
        const int kbase = qb - 256 + 64 * t;
        #pragma unroll
        for (int i = 0; i < 2; i++) {
            const int id = tid + i * 256, r = id >> 3, c = id & 7;
            int j = kbase + r; j = j < 0 ? 0 : (j >= SS ? SS - 1 : j);
            cp16(sKb[buf] + arow_off(r, c), (const char*)(Kg + (rowbase + j) * C3) + c * 16);
            cp16(sVb[buf] + arow_off(r, c), (const char*)(Vg + (rowbase + j) * C3) + c * 16);
        }
    };

    issue(tstart, 0);
    cp_commit();

    uint32_t aq[4][4];
    float acc_o[8][4] = {};
    float m0 = -1e30f, m1 = -1e30f, l0 = 0.f, l1 = 0.f;
    const int i0 = qb + w * 16 + g;
    const int i1 = i0 + 8;

    for (int t = tstart; t <= tend; t++) {
        const int buf = (t - tstart) & 1;
        if (t < tend) { issue(t + 1, buf ^ 1); cp_commit(); }
        if (t < tend) asm volatile("cp.async.wait_group 1;" ::: "memory");
        else          asm volatile("cp.async.wait_group 0;" ::: "memory");
        __syncthreads();

        if (t == tstart) {
            #pragma unroll
            for (int ks = 0; ks < 4; ks++) {
                const int row = w * 16 + (lane & 7) + ((lane >> 3) & 1) * 8;
                const int ch  = 2 * ks + (lane >> 4);
                ldsm4(aq[ks], sQb + arow_off(row, ch));
            }
        }

        const int kbase = qb - 256 + 64 * t;

        // ---- scores S = Q K^T ----
        float s[8][4] = {};
        #pragma unroll
        for (int ks = 0; ks < 4; ks++) {
            uint32_t bk[4][4];
            #pragma unroll
            for (int n2 = 0; n2 < 4; n2++) {
                const int row = n2 * 16 + (lane & 7) + ((lane >> 3) & 1) * 8;
                const int ch  = 2 * ks + (lane >> 4);
                ldsm4(bk[n2], sKb[buf] + arow_off(row, ch));
            }
            #pragma unroll
            for (int ni = 0; ni < 8; ni++)
                mma_f16(s[ni], aq[ks], bk[ni >> 1][ni & 1], bk[ni >> 1][2 + (ni & 1)]);
        }

        // ---- mask (tiles fully inside window & seq: 2..7 interior) ----
        const bool masked = (t <= 1) | (t >= 8) | (kbase < 0) | (kbase + 63 >= SS);
        if (masked) {
            #pragma unroll
            for (int ni = 0; ni < 8; ni++) {
                #pragma unroll
                for (int c = 0; c < 2; c++) {
                    const int j = kbase + ni * 8 + 2 * tg + c;
                    const bool inseq = (j >= 0) & (j < SS);
                    if (!(inseq & (j >= i0 - WW) & (j <= i0 + WW))) s[ni][c]     = -1e30f;
                    if (!(inseq & (j >= i1 - WW) & (j <= i1 + WW))) s[ni][c + 2] = -1e30f;
                }
            }
        }

        // ---- online softmax ----
        float mx0 = s[0][0], mx1 = s[0][2];
        #pragma unroll
        for (int ni = 0; ni < 8; ni++) {
            mx0 = fmaxf(mx0, fmaxf(s[ni][0], s[ni][1]));
            mx1 = fmaxf(mx1, fmaxf(s[ni][2], s[ni][3]));
        }
        mx0 = fmaxf(mx0, __shfl_xor_sync(0xffffffffu, mx0, 1));
        mx0 = fmaxf(mx0, __shfl_xor_sync(0xffffffffu, mx0, 2));
        mx1 = fmaxf(mx1, __shfl_xor_sync(0xffffffffu, mx1, 1));
        mx1 = fmaxf(mx1, __shfl_xor_sync(0xffffffffu, mx1, 2));
        const float mn0 = fmaxf(m0, mx0), mn1 = fmaxf(m1, mx1);
        const float f0 = ex2((m0 - mn0) * ASC), f1 = ex2((m1 - mn1) * ASC);
        m0 = mn0; m1 = mn1;

        float ps0 = 0.f, ps1 = 0.f;
        #pragma unroll
        for (int ni = 0; ni < 8; ni++) {
            s[ni][0] = ex2((s[ni][0] - mn0) * ASC);
            s[ni][1] = ex2((s[ni][1] - mn0) * ASC);
            s[ni][2] = ex2((s[ni][2] - mn1) * ASC);
            s[ni][3] = ex2((s[ni][3] - mn1) * ASC);
            ps0 += s[ni][0] + s[ni][1];
            ps1 += s[ni][2] + s[ni][3];
        }
        // per-thread partials; quad-reduced once after the loop
        l0 = l0 * f0 + ps0;
        l1 = l1 * f1 + ps1;
        #pragma unroll
        for (int nd = 0; nd < 8; nd++) {
            acc_o[nd][0] *= f0; acc_o[nd][1] *= f0;
            acc_o[nd][2] *= f1; acc_o[nd][3] *= f1;
        }

        // ---- PV: O += P V ----
        #pragma unroll
        for (int kk = 0; kk < 4; kk++) {
            uint32_t pa[4];
            pa[0] = pack_h2(s[2*kk][0],   s[2*kk][1]);
            pa[1] = pack_h2(s[2*kk][2],   s[2*kk][3]);
            pa[2] = pack_h2(s[2*kk+1][0], s[2*kk+1][1]);
            pa[3] = pack_h2(s[2*kk+1][2], s[2*kk+1][3]);
            #pragma unroll
            for (int d2 = 0; d2 < 4; d2++) {
                uint32_t bv[4];
                const int row = kk * 16 + (lane & 7) + ((lane >> 3) & 1) * 8;
                const int ch  = 2 * d2 + (lane >> 4);
                ldsm4t(bv, sVb[buf] + arow_off(row, ch));
                mma_f16(acc_o[2 * d2],     pa, bv[0], bv[1]);
                mma_f16(acc_o[2 * d2 + 1], pa, bv[2], bv[3]);
            }
        }
        __syncthreads();
    }

    // reduce softmax denominator across the quad
    l0 += __shfl_xor_sync(0xffffffffu, l0, 1);
    l0 += __shfl_xor_sync(0xffffffffu, l0, 2);
    l1 += __shfl_xor_sync(0xffffffffu, l1, 1);
    l1 += __shfl_xor_sync(0xffffffffu, l1, 2);

    // ---- write out ----
    const float r0 = 1.f / l0, r1 = 1.f / l1;
    __half* o0 = out + (rowbase + i0) * EE + h * DD + 2 * tg;
    __half* o1 = out + (rowbase + i1) * EE + h * DD + 2 * tg;
    #pragma unroll
    for (int nd = 0; nd < 8; nd++) {
        *(__half2*)(o0 + nd * 8) = __floats2half2_rn(acc_o[nd][0] * r0, acc_o[nd][1] * r0);
        *(__half2*)(o1 + nd * 8) = __floats2half2_rn(acc_o[nd][2] * r1, acc_o[nd][3] * r1);
    }
}

// ---------------- launch ----------------
extern "C" void kernel_launch(void* const* d_in, const int* in_sizes, int n_in,
                              void* d_out, int out_size)
{
    const float* x        = (const float*)d_in[0];
    const float* ln1_g    = (const float*)d_in[1];
    const float* ln1_b    = (const float*)d_in[2];
    const float* c_attn_w = (const float*)d_in[3];
    const float* c_attn_b = (const float*)d_in[4];
    const float* c_proj_w = (const float*)d_in[5];
    const float* c_proj_b = (const float*)d_in[6];
    const float* ln2_g    = (const float*)d_in[7];
    const float* ln2_b    = (const float*)d_in[8];
    const float* fc_w     = (const float*)d_in[9];
    const float* fc_b     = (const float*)d_in[10];
    const float* proj2_w  = (const float*)d_in[11];
    const float* proj2_b  = (const float*)d_in[12];
    float* out = (float*)d_out;

    __half *h, *qkv, *attn, *ff;
    float *x1;
    __half *wT_attn, *wT_proj, *wT_fc, *wT_proj2;
    cudaGetSymbolAddress((void**)&h,    g_buf_h);
    cudaGetSymbolAddress((void**)&qkv,  g_buf_qkv);
    cudaGetSymbolAddress((void**)&attn, g_buf_attn);
    cudaGetSymbolAddress((void**)&x1,   g_buf_x1);
    cudaGetSymbolAddress((void**)&ff,   g_buf_ff);
    cudaGetSymbolAddress((void**)&wT_attn,  g_wT_attn);
    cudaGetSymbolAddress((void**)&wT_proj,  g_wT_proj);
    cudaGetSymbolAddress((void**)&wT_fc,    g_wT_fc);
    cudaGetSymbolAddress((void**)&wT_proj2, g_wT_proj2);

    cudaFuncSetAttribute(hgemm<0>, cudaFuncAttributeMaxDynamicSharedMemorySize, HG_SMEM);
    cudaFuncSetAttribute(hgemm<1>, cudaFuncAttributeMaxDynamicSharedMemorySize, HG_SMEM);
    cudaFuncSetAttribute(hgemm<2>, cudaFuncAttributeMaxDynamicSharedMemorySize, HG_SMEM);
    cudaFuncSetAttribute(attn_kernel, cudaFuncAttributeMaxDynamicSharedMemorySize, AT_SMEM);

    transpose_all<<<NT0 + NT1 + NT2 + NT3, 256>>>(
        c_attn_w, wT_attn, c_proj_w, wT_proj, fc_w, wT_fc, proj2_w, wT_proj2);

    ln_kernel<<<ROWS, 256>>>(x, ln1_g, ln1_b, h);
    hgemm<0><<<dim3(C3 / 128, ROWS / 128), 256, HG_SMEM>>>(
        h, wT_attn, c_attn_b, nullptr, qkv, ROWS, C3, EE);
    attn_kernel<<<dim3(SS / 128, HH, BB), 256, AT_SMEM>>>(qkv, attn);
    hgemm<1><<<dim3(EE / 128, ROWS / 128), 256, HG_SMEM>>>(
        attn, wT_proj, c_proj_b, x, x1, ROWS, EE, EE);
    ln_kernel<<<ROWS, 256>>>(x1, ln2_g, ln2_b, h);
    hgemm<2><<<dim3(E4 / 128, ROWS / 128), 256, HG_SMEM>>>(
        h, wT_fc, fc_b, nullptr, ff, ROWS, E4, EE);
    hgemm<1><<<dim3(EE / 128, ROWS / 128), 256, HG_SMEM>>>(
        ff, wT_proj2, proj2_b, x1, out, ROWS, EE, E4);
}